// round 2
// baseline (speedup 1.0000x reference)
#include <cuda_runtime.h>
#include <math.h>

// Problem constants
#define NBLK 128
#define TPB  256
#define BB   64     // batch
#define TT   256    // time steps
#define DD   512    // hidden
#define WW   256    // output width
#define FF   256    // cond features
#define G4D  2048   // 4*DD

// -------- persistent state (device globals; no allocs allowed) --------
__device__ float g_h[2][2][BB][DD];   // [parity][layer][b][d]
__device__ float g_c[2][BB][DD];      // [layer][b][d] (thread-private across steps)
__device__ float g_xin[BB][DD];
__device__ float g_prev[BB][WW];
__device__ float g_cbias[BB][DD];     // b_in + cond @ W_in[256:]
__device__ unsigned int g_arrive;
__device__ unsigned int g_gen;

__device__ __forceinline__ float sigf(float x) { return 1.0f / (1.0f + expf(-x)); }

// Sense-reversing grid barrier. 128 CTAs, all co-resident (1 per SM, 148 SMs).
__device__ __forceinline__ void grid_barrier() {
    __syncthreads();
    if (threadIdx.x == 0) {
        __threadfence();
        unsigned gen = *((volatile unsigned int*)&g_gen);
        unsigned old = atomicAdd(&g_arrive, 1);
        if (old == NBLK - 1) {
            g_arrive = 0;
            __threadfence();
            atomicAdd(&g_gen, 1);
        } else {
            while (*((volatile unsigned int*)&g_gen) == gen) { __nanosleep(64); }
        }
        __threadfence();
    }
    __syncthreads();
}

// ============================================================================
// P0: xin[64,512] = g_prev[64,256] @ W_in[0:256,:] + g_cbias
// Block covers 4 output cols. 8-way K-split across warps, per-thread 4b x 2c.
// ============================================================================
__device__ void phase_p0(const float* __restrict__ W_in, float* sm) {
    const int tid = threadIdx.x;
    const int ks = tid >> 5, lane = tid & 31;
    const int bg = lane >> 1, cg = lane & 1;
    const int nbase = blockIdx.x * 4;

    float acc[8];
#pragma unroll
    for (int m = 0; m < 8; m++) acc[m] = 0.0f;

    float* myA = sm + ks * 512;          // [8 j][64 b] transposed
    float* myW = sm + 4096 + ks * 32;    // [8 j][4 c]
    const int kb0 = ks * 32;             // K=256 split 8 ways

    for (int ch = 0; ch < 4; ch++) {
        const int kb = kb0 + ch * 8;
        // stage A (transposed): g_prev[b][kb..kb+8)
#pragma unroll
        for (int r = 0; r < 8; r++) {
            int idx = r * 32 + lane;
            int b = idx >> 2, jp = idx & 3;
            float2 v = __ldcg((const float2*)(&g_prev[b][kb + jp * 2]));
            myA[jp * 128 + b] = v.x;
            myA[jp * 128 + 64 + b] = v.y;
        }
        // stage W: 8 k rows x 4 cols
        if (lane < 8) {
            float4 wv = *(const float4*)(W_in + (kb + lane) * DD + nbase);
            *(float4*)(myW + lane * 4) = wv;
        }
        __syncwarp();
#pragma unroll
        for (int j = 0; j < 8; j++) {
            float4 av = *(const float4*)(myA + j * 64 + bg * 4);
            float2 wv = *(const float2*)(myW + j * 4 + cg * 2);
            float a[4] = {av.x, av.y, av.z, av.w};
#pragma unroll
            for (int i = 0; i < 4; i++) {
                acc[i * 2 + 0] = fmaf(a[i], wv.x, acc[i * 2 + 0]);
                acc[i * 2 + 1] = fmaf(a[i], wv.y, acc[i * 2 + 1]);
            }
        }
        __syncwarp();
    }

    // cross-warp K reduction
    __syncthreads();
#pragma unroll
    for (int m = 0; m < 8; m++) sm[tid * 33 + m] = acc[m];
    __syncthreads();
    if (tid < 128) {
#pragma unroll
        for (int m = 0; m < 8; m++) sm[tid * 33 + m] += sm[(tid + 128) * 33 + m];
    }
    __syncthreads();
    if (tid < 64) {
#pragma unroll
        for (int m = 0; m < 8; m++) sm[tid * 33 + m] += sm[(tid + 64) * 33 + m];
    }
    __syncthreads();
    if (tid < 32) {
#pragma unroll
        for (int m = 0; m < 8; m++) sm[tid * 33 + m] += sm[(tid + 32) * 33 + m];
    }
    __syncthreads();

    // epilogue: one (b,q) per thread
    {
        const int b = tid >> 2, q = tid & 3;
        float z = sm[(((b >> 2) * 2) + (q >> 1)) * 33 + (b & 3) * 2 + (q & 1)];
        g_xin[b][nbase + q] = z + g_cbias[b][nbase + q];
    }
}

// ============================================================================
// Layer: z[64,2048] = X[64,512]@Kw + H[64,512]@Rw + bias ; gates ; c,h update.
// Block covers 4 n-cols (16 scalar cols = 4n x 4gates).
// 8-way K-split (warps 0-3: X/Kw, warps 4-7: H/Rw). Per-thread 4b x 8c tile.
// ============================================================================
__device__ void phase_layer(const float* __restrict__ X, const float* __restrict__ Hin,
                            const float* __restrict__ Kw, const float* __restrict__ Rw,
                            const float* __restrict__ bias,
                            float* __restrict__ Cst, float* __restrict__ Hout,
                            float* sm) {
    const int tid = threadIdx.x;
    const int ks = tid >> 5, lane = tid & 31;
    const int bg = lane >> 1, cg = lane & 1;
    const int nbase = blockIdx.x * 4;

    float acc[32];
#pragma unroll
    for (int m = 0; m < 32; m++) acc[m] = 0.0f;

    float* myA = sm + ks * 512;           // [8 j][64 b] transposed
    float* myW = sm + 4096 + ks * 128;    // [8 j][16 c], c = gate*4 + q
    const float* Asrc = (ks < 4) ? X : Hin;
    const float* Wsrc = (ks < 4) ? Kw : Rw;
    const int kb0 = (ks & 3) * 128;

    for (int ch = 0; ch < 16; ch++) {
        const int kb = kb0 + ch * 8;
        // stage A transposed: Asrc[b][kb..kb+8) -> myA[j][b]
#pragma unroll
        for (int r = 0; r < 8; r++) {
            int idx = r * 32 + lane;
            int b = idx >> 2, jp = idx & 3;
            float2 v = __ldcg((const float2*)(Asrc + b * DD + kb + jp * 2));
            myA[jp * 128 + b] = v.x;
            myA[jp * 128 + 64 + b] = v.y;
        }
        // stage W: 8 k rows x (4 gates x 4 cols); one float4 per lane
        {
            int kr = lane >> 2, g = lane & 3;
            float4 wv = *(const float4*)(Wsrc + (kb + kr) * G4D + g * DD + nbase);
            *(float4*)(myW + kr * 16 + g * 4) = wv;
        }
        __syncwarp();
#pragma unroll
        for (int j = 0; j < 8; j++) {
            float4 av = *(const float4*)(myA + j * 64 + bg * 4);
            float4 w0 = *(const float4*)(myW + j * 16 + cg * 8);
            float4 w1 = *(const float4*)(myW + j * 16 + cg * 8 + 4);
            float a[4] = {av.x, av.y, av.z, av.w};
            float w[8] = {w0.x, w0.y, w0.z, w0.w, w1.x, w1.y, w1.z, w1.w};
#pragma unroll
            for (int i = 0; i < 4; i++)
#pragma unroll
                for (int jj = 0; jj < 8; jj++)
                    acc[i * 8 + jj] = fmaf(a[i], w[jj], acc[i * 8 + jj]);
        }
        __syncwarp();
    }

    // cross-warp K reduction: rows [tid][33-padded]
    __syncthreads();
#pragma unroll
    for (int m = 0; m < 32; m++) sm[tid * 33 + m] = acc[m];
    __syncthreads();
    if (tid < 128) {
#pragma unroll
        for (int m = 0; m < 32; m++) sm[tid * 33 + m] += sm[(tid + 128) * 33 + m];
    }
    __syncthreads();
    if (tid < 64) {
#pragma unroll
        for (int m = 0; m < 32; m++) sm[tid * 33 + m] += sm[(tid + 64) * 33 + m];
    }
    __syncthreads();
    if (tid < 32) {
#pragma unroll
        for (int m = 0; m < 32; m++) sm[tid * 33 + m] += sm[(tid + 32) * 33 + m];
    }
    __syncthreads();

    // gate epilogue: one (b, q) per thread; z(b,c) at row=(b>>2)*2+(c>>3), m=(b&3)*8+(c&7)
    {
        const int b = tid >> 2, q = tid & 3;
        const int n = nbase + q;
#define ZRD(c) sm[(((b >> 2) * 2) + ((c) >> 3)) * 33 + (b & 3) * 8 + ((c) & 7)]
        float zi = ZRD(q)      + bias[n];
        float zf = ZRD(4 + q)  + bias[DD + n];
        float zg = ZRD(8 + q)  + bias[2 * DD + n];
        float zo = ZRD(12 + q) + bias[3 * DD + n];
#undef ZRD
        float co = Cst[b * DD + n];
        float ig = sigf(zi), fg = sigf(zf), gg = tanhf(zg), og = sigf(zo);
        float cn = fg * co + ig * gg;
        float hn = og * tanhf(cn);
        Cst[b * DD + n] = cn;
        Hout[b * DD + n] = hn;
    }
}

// ============================================================================
// P3: out[64,256] = sigmoid(h1[64,512] @ W_out + b_out); write d_out & g_prev.
// Block covers 2 cols. 8-way K-split, per-thread 2b x 2c.
// ============================================================================
__device__ void phase_p3(const float* __restrict__ Hsrc, const float* __restrict__ W_out,
                         const float* __restrict__ b_out, float* __restrict__ dout,
                         int t, float* sm) {
    const int tid = threadIdx.x;
    const int ks = tid >> 5, lane = tid & 31;
    const int cbase = blockIdx.x * 2;

    float acc[4] = {0.0f, 0.0f, 0.0f, 0.0f};
    float* myA = sm + ks * 512;          // [8 j][64 b]
    float* myW = sm + 4096 + ks * 16;    // [8 j][2 c]
    const int kb0 = ks * 64;             // K=512 split 8 ways

    for (int ch = 0; ch < 8; ch++) {
        const int kb = kb0 + ch * 8;
#pragma unroll
        for (int r = 0; r < 8; r++) {
            int idx = r * 32 + lane;
            int b = idx >> 2, jp = idx & 3;
            float2 v = __ldcg((const float2*)(Hsrc + b * DD + kb + jp * 2));
            myA[jp * 128 + b] = v.x;
            myA[jp * 128 + 64 + b] = v.y;
        }
        if (lane < 8) {
            float2 wv = *(const float2*)(W_out + (kb + lane) * WW + cbase);
            *(float2*)(myW + lane * 2) = wv;
        }
        __syncwarp();
#pragma unroll
        for (int j = 0; j < 8; j++) {
            float2 av = *(const float2*)(myA + j * 64 + lane * 2);
            float2 wv = *(const float2*)(myW + j * 2);
            acc[0] = fmaf(av.x, wv.x, acc[0]);
            acc[1] = fmaf(av.x, wv.y, acc[1]);
            acc[2] = fmaf(av.y, wv.x, acc[2]);
            acc[3] = fmaf(av.y, wv.y, acc[3]);
        }
        __syncwarp();
    }

    __syncthreads();
#pragma unroll
    for (int m = 0; m < 4; m++) sm[tid * 33 + m] = acc[m];
    __syncthreads();
    if (tid < 128) {
#pragma unroll
        for (int m = 0; m < 4; m++) sm[tid * 33 + m] += sm[(tid + 128) * 33 + m];
    }
    __syncthreads();
    if (tid < 64) {
#pragma unroll
        for (int m = 0; m < 4; m++) sm[tid * 33 + m] += sm[(tid + 64) * 33 + m];
    }
    __syncthreads();
    if (tid < 32) {
#pragma unroll
        for (int m = 0; m < 4; m++) sm[tid * 33 + m] += sm[(tid + 32) * 33 + m];
    }
    __syncthreads();

    if (tid < 128) {
        const int b = tid >> 1, c = tid & 1;
        float z = sm[(b >> 1) * 33 + (b & 1) * 2 + c];
        float v = sigf(z + b_out[cbase + c]);
        dout[(b * TT + t) * WW + cbase + c] = v;
        g_prev[b][cbase + c] = v;
    }
}

// ============================================================================
// Persistent kernel: init state, then T steps of (P0, L0, L1, P3) with grid
// barriers. 128 CTAs x 256 threads, 1 CTA/SM -> co-residency guaranteed.
// ============================================================================
__global__ void __launch_bounds__(TPB, 1)
lstm_persistent_kernel(const float* __restrict__ inputs,
                       const float* __restrict__ rand_prev,
                       const float* __restrict__ init_h,
                       const float* __restrict__ init_c,
                       const float* __restrict__ W_in,
                       const float* __restrict__ b_in,
                       const float* __restrict__ kernels,
                       const float* __restrict__ rec_kernels,
                       const float* __restrict__ biases,
                       const float* __restrict__ W_out,
                       const float* __restrict__ b_out,
                       float* __restrict__ out) {
    __shared__ float sm[8448];  // max(staging 20KB, reduction 256x33 = 33KB)
    const int tid = threadIdx.x;
    const int gt = blockIdx.x * TPB + tid;
    const int gstride = NBLK * TPB;

    // ---- PINIT: reload state every launch (graph replays!) ----
    for (int i = gt; i < 2 * BB * DD; i += gstride) {
        (&g_h[0][0][0][0])[i] = init_h[i];
        (&g_c[0][0][0])[i] = init_c[i];
    }
    for (int i = gt; i < BB * WW; i += gstride) {
        (&g_prev[0][0])[i] = rand_prev[i];
    }
    // cbias = b_in + cond @ W_in[256:,:]   (time-invariant)
    for (int i = gt; i < BB * DD; i += gstride) {
        const int b = i >> 9, dc = i & (DD - 1);
        const float* cn = inputs + b * FF;  // inputs[b,0,:]
        float s = b_in[dc];
#pragma unroll 4
        for (int k = 0; k < FF; k++)
            s = fmaf(cn[k], W_in[(WW + k) * DD + dc], s);
        (&g_cbias[0][0])[i] = s;
    }
    grid_barrier();

    const float* Kw0 = kernels;
    const float* Kw1 = kernels + DD * G4D;
    const float* Rw0 = rec_kernels;
    const float* Rw1 = rec_kernels + DD * G4D;
    const float* bs0 = biases;
    const float* bs1 = biases + G4D;

    for (int t = 0; t < TT; t++) {
        const int p = t & 1;
        phase_p0(W_in, sm);
        grid_barrier();
        phase_layer(&g_xin[0][0], &g_h[p][0][0][0], Kw0, Rw0, bs0,
                    &g_c[0][0][0], &g_h[1 - p][0][0][0], sm);
        grid_barrier();
        phase_layer(&g_h[1 - p][0][0][0], &g_h[p][1][0][0], Kw1, Rw1, bs1,
                    &g_c[1][0][0], &g_h[1 - p][1][0][0], sm);
        grid_barrier();
        phase_p3(&g_h[1 - p][1][0][0], W_out, b_out, out, t, sm);
        grid_barrier();
    }
}

extern "C" void kernel_launch(void* const* d_in, const int* in_sizes, int n_in,
                              void* d_out, int out_size) {
    const float* inputs      = (const float*)d_in[0];
    const float* rand_prev   = (const float*)d_in[1];
    const float* init_h      = (const float*)d_in[2];
    const float* init_c      = (const float*)d_in[3];
    const float* W_in        = (const float*)d_in[4];
    const float* b_in        = (const float*)d_in[5];
    const float* kernels     = (const float*)d_in[6];
    const float* rec_kernels = (const float*)d_in[7];
    const float* biases      = (const float*)d_in[8];
    const float* W_out       = (const float*)d_in[9];
    const float* b_out       = (const float*)d_in[10];
    float* out = (float*)d_out;

    lstm_persistent_kernel<<<NBLK, TPB>>>(inputs, rand_prev, init_h, init_c,
                                          W_in, b_in, kernels, rec_kernels,
                                          biases, W_out, b_out, out);
}

// round 3
// speedup vs baseline: 1.3073x; 1.3073x over previous
#include <cuda_runtime.h>
#include <math.h>

// Problem constants
#define NBLK 128
#define TPB  256
#define BB   64     // batch
#define TT   256    // time steps
#define DD   512    // hidden
#define WW   256    // output width
#define FF   256    // cond features
#define G4D  2048   // 4*DD

// -------- dynamic smem layout (float offsets) --------
// W0: 768 rows x 16 cols. rows 0..255 = M0 (= W_in[0:256]@K0 slice), rows 256..767 = R0
// W1: 1024 rows x 16 cols. rows 0..511 = K1, rows 512..1023 = R1
#define OFF_W0   0         // 12288 floats
#define OFF_W1   12288     // 16384 floats
#define OFF_WOUT 28672     // 1024 floats (512 x 2)
#define OFF_CVEC 29696     // 1024 floats (64 b x 16 c)  = cbias@K0 slice
#define OFF_BIAS 30720     // 64 floats: [0:16)=bias L0, [16:32)=bias L1, [32:34)=b_out
#define OFF_WORK 30784     // 8448 floats: A staging (8 warps x 1024) aliased with reduction (256x33)
#define SMEM_FLOATS 39232
#define SMEM_BYTES (SMEM_FLOATS * 4)

// -------- persistent device state --------
__device__ float g_h[2][2][BB][DD];   // [parity][layer][b][d]
__device__ float g_c[2][BB][DD];
__device__ float g_prev[BB][WW];
__device__ float g_cbias[BB][DD];     // b_in + cond @ W_in[256:]
__device__ unsigned int g_arrive;
__device__ unsigned int g_gen;

__device__ __forceinline__ float sigf(float x) { return 1.0f / (1.0f + expf(-x)); }

// Sense-reversing grid barrier (128 CTAs, 1/SM, co-resident). Tight spin, no sleep.
__device__ __forceinline__ void grid_barrier() {
    __syncthreads();
    if (threadIdx.x == 0) {
        __threadfence();
        unsigned gen = *((volatile unsigned int*)&g_gen);
        unsigned old = atomicAdd(&g_arrive, 1);
        if (old == NBLK - 1) {
            g_arrive = 0;
            __threadfence();
            atomicAdd(&g_gen, 1);
        } else {
            while (*((volatile unsigned int*)&g_gen) == gen) { }
        }
        __threadfence();
    }
    __syncthreads();
}

// ============================================================================
// LSTM layer phase. z[64, 16cols] = A[64, Klen] @ smW[Klen,16] (+bias +cvec),
// A = concat(A0 [len A0len], A1). 8-way K-split across warps, per-thread 4b x 8c.
// Weights in smem; A staged via register-prefetch -> smem double buffer.
// ============================================================================
__device__ __noinline__ void phase_L(
    const float* __restrict__ A0, int A0len, int A0str,
    const float* __restrict__ A1, int A1str,
    int Klen,
    const float* __restrict__ smW, const float* __restrict__ smBias,
    const float* __restrict__ smCvec,
    float* __restrict__ Cst, float* __restrict__ Hout,
    float* __restrict__ sm)
{
    const int tid = threadIdx.x;
    const int ks = tid >> 5, lane = tid & 31;
    const int bg = lane >> 1, cg = lane & 1;
    const int nbase = blockIdx.x * 4;
    const int kperw = Klen >> 3;        // 96 or 128
    const int nch = kperw >> 3;         // 12 or 16
    const int kb0 = ks * kperw;

    float acc[32];
#pragma unroll
    for (int m = 0; m < 32; m++) acc[m] = 0.0f;

    float* buf = sm + OFF_WORK + ks * 1024;   // 2 x 512 double buffer per warp
    float2 pf[8];

    // prefetch chunk 0
    {
        const int kbA = kb0;
        const float* ap; int as;
        if (kbA < A0len) { ap = A0 + kbA; as = A0str; }
        else             { ap = A1 + (kbA - A0len); as = A1str; }
#pragma unroll
        for (int r = 0; r < 8; r++) {
            int idx = r * 32 + lane, b = idx >> 2, jp = idx & 3;
            pf[r] = __ldcg((const float2*)(ap + b * as + jp * 2));
        }
    }

    for (int ch = 0; ch < nch; ch++) {
        float* mb = buf + (ch & 1) * 512;
        // store staged chunk (transposed [j][b])
#pragma unroll
        for (int r = 0; r < 8; r++) {
            int idx = r * 32 + lane, b = idx >> 2, jp = idx & 3;
            mb[(jp * 2) * 64 + b]     = pf[r].x;
            mb[(jp * 2 + 1) * 64 + b] = pf[r].y;
        }
        // prefetch next chunk while computing this one
        if (ch + 1 < nch) {
            const int kbA = kb0 + (ch + 1) * 8;
            const float* ap; int as;
            if (kbA < A0len) { ap = A0 + kbA; as = A0str; }
            else             { ap = A1 + (kbA - A0len); as = A1str; }
#pragma unroll
            for (int r = 0; r < 8; r++) {
                int idx = r * 32 + lane, b = idx >> 2, jp = idx & 3;
                pf[r] = __ldcg((const float2*)(ap + b * as + jp * 2));
            }
        }
        __syncwarp();
        const float* wr = smW + (kb0 + ch * 8) * 16;
#pragma unroll
        for (int j = 0; j < 8; j++) {
            float4 av = *(const float4*)(mb + j * 64 + bg * 4);
            float4 w0 = *(const float4*)(wr + j * 16 + cg * 8);
            float4 w1 = *(const float4*)(wr + j * 16 + cg * 8 + 4);
            float a[4] = {av.x, av.y, av.z, av.w};
            float w[8] = {w0.x, w0.y, w0.z, w0.w, w1.x, w1.y, w1.z, w1.w};
#pragma unroll
            for (int i = 0; i < 4; i++)
#pragma unroll
                for (int jj = 0; jj < 8; jj++)
                    acc[i * 8 + jj] = fmaf(a[i], w[jj], acc[i * 8 + jj]);
        }
    }

    // cross-warp K reduction
    float* rb = sm + OFF_WORK;
    __syncthreads();
#pragma unroll
    for (int m = 0; m < 32; m++) rb[tid * 33 + m] = acc[m];
    __syncthreads();
    if (tid < 128) {
#pragma unroll
        for (int m = 0; m < 32; m++) rb[tid * 33 + m] += rb[(tid + 128) * 33 + m];
    }
    __syncthreads();
    if (tid < 64) {
#pragma unroll
        for (int m = 0; m < 32; m++) rb[tid * 33 + m] += rb[(tid + 64) * 33 + m];
    }
    __syncthreads();
    if (tid < 32) {
#pragma unroll
        for (int m = 0; m < 32; m++) rb[tid * 33 + m] += rb[(tid + 32) * 33 + m];
    }
    __syncthreads();

    // gate epilogue: one (b, q) per thread
    {
        const int b = tid >> 2, q = tid & 3;
        const int n = nbase + q;
#define ZRD(c) rb[(((b >> 2) * 2) + ((c) >> 3)) * 33 + (b & 3) * 8 + ((c) & 7)]
        float cvi = 0.0f, cvf = 0.0f, cvg = 0.0f, cvo = 0.0f;
        if (smCvec) {
            cvi = smCvec[b * 16 + q];
            cvf = smCvec[b * 16 + 4 + q];
            cvg = smCvec[b * 16 + 8 + q];
            cvo = smCvec[b * 16 + 12 + q];
        }
        float zi = ZRD(q)      + smBias[q]      + cvi;
        float zf = ZRD(4 + q)  + smBias[4 + q]  + cvf;
        float zg = ZRD(8 + q)  + smBias[8 + q]  + cvg;
        float zo = ZRD(12 + q) + smBias[12 + q] + cvo;
#undef ZRD
        float co = Cst[b * DD + n];
        float ig = sigf(zi), fg = sigf(zf), gg = tanhf(zg), og = sigf(zo);
        float cn = fg * co + ig * gg;
        float hn = og * tanhf(cn);
        Cst[b * DD + n] = cn;
        Hout[b * DD + n] = hn;
    }
}

// ============================================================================
// P3: out[64,256] = sigmoid(h1 @ W_out + b_out). Block covers 2 cols.
// ============================================================================
__device__ __noinline__ void phase_p3(const float* __restrict__ Hsrc,
                                      const float* __restrict__ smWO,
                                      const float* __restrict__ smBias,
                                      float* __restrict__ dout, int t,
                                      float* __restrict__ sm)
{
    const int tid = threadIdx.x;
    const int ks = tid >> 5, lane = tid & 31;
    const int cbase = blockIdx.x * 2;
    const int kb0 = ks * 64;

    float acc[4] = {0.0f, 0.0f, 0.0f, 0.0f};
    float* buf = sm + OFF_WORK + ks * 1024;
    float2 pf[8];

#pragma unroll
    for (int r = 0; r < 8; r++) {
        int idx = r * 32 + lane, b = idx >> 2, jp = idx & 3;
        pf[r] = __ldcg((const float2*)(Hsrc + b * DD + kb0 + jp * 2));
    }

    for (int ch = 0; ch < 8; ch++) {
        float* mb = buf + (ch & 1) * 512;
#pragma unroll
        for (int r = 0; r < 8; r++) {
            int idx = r * 32 + lane, b = idx >> 2, jp = idx & 3;
            mb[(jp * 2) * 64 + b]     = pf[r].x;
            mb[(jp * 2 + 1) * 64 + b] = pf[r].y;
        }
        if (ch + 1 < 8) {
            const int kb = kb0 + (ch + 1) * 8;
#pragma unroll
            for (int r = 0; r < 8; r++) {
                int idx = r * 32 + lane, b = idx >> 2, jp = idx & 3;
                pf[r] = __ldcg((const float2*)(Hsrc + b * DD + kb + jp * 2));
            }
        }
        __syncwarp();
        const float* wr = smWO + (kb0 + ch * 8) * 2;
#pragma unroll
        for (int j = 0; j < 8; j++) {
            float2 av = *(const float2*)(mb + j * 64 + lane * 2);
            float2 wv = *(const float2*)(wr + j * 2);
            acc[0] = fmaf(av.x, wv.x, acc[0]);
            acc[1] = fmaf(av.x, wv.y, acc[1]);
            acc[2] = fmaf(av.y, wv.x, acc[2]);
            acc[3] = fmaf(av.y, wv.y, acc[3]);
        }
    }

    float* rb = sm + OFF_WORK;
    __syncthreads();
#pragma unroll
    for (int m = 0; m < 4; m++) rb[tid * 33 + m] = acc[m];
    __syncthreads();
    if (tid < 128) {
#pragma unroll
        for (int m = 0; m < 4; m++) rb[tid * 33 + m] += rb[(tid + 128) * 33 + m];
    }
    __syncthreads();
    if (tid < 64) {
#pragma unroll
        for (int m = 0; m < 4; m++) rb[tid * 33 + m] += rb[(tid + 64) * 33 + m];
    }
    __syncthreads();
    if (tid < 32) {
#pragma unroll
        for (int m = 0; m < 4; m++) rb[tid * 33 + m] += rb[(tid + 32) * 33 + m];
    }
    __syncthreads();

    if (tid < 128) {
        const int b = tid >> 1, c = tid & 1;
        float z = rb[(b >> 1) * 33 + (b & 1) * 2 + c];
        float v = sigf(z + smBias[32 + c]);
        dout[(b * TT + t) * WW + cbase + c] = v;
        g_prev[b][cbase + c] = v;
    }
}

// ============================================================================
// Persistent kernel
// ============================================================================
__global__ void __launch_bounds__(TPB, 1)
lstm_persistent_kernel(const float* __restrict__ inputs,
                       const float* __restrict__ rand_prev,
                       const float* __restrict__ init_h,
                       const float* __restrict__ init_c,
                       const float* __restrict__ W_in,
                       const float* __restrict__ b_in,
                       const float* __restrict__ kernels,
                       const float* __restrict__ rec_kernels,
                       const float* __restrict__ biases,
                       const float* __restrict__ W_out,
                       const float* __restrict__ b_out,
                       float* __restrict__ out) {
    extern __shared__ float sm[];
    const int tid = threadIdx.x;
    const int nbase = blockIdx.x * 4;
    const int cbase = blockIdx.x * 2;
    const int gt = blockIdx.x * TPB + tid;
    const int gstride = NBLK * TPB;

    // ---- weight preload into smem ----
    // W0 rows 256..767 = R0 (layer 0 recurrent)
    for (int idx = tid; idx < 512 * 16; idx += TPB) {
        int row = idx >> 4, c = idx & 15, g = c >> 2, q = c & 3;
        sm[OFF_W0 + (256 + row) * 16 + c] = rec_kernels[row * G4D + g * DD + nbase + q];
    }
    // W1: rows 0..511 = K1, rows 512..1023 = R1
    for (int idx = tid; idx < 1024 * 16; idx += TPB) {
        int row = idx >> 4, c = idx & 15, g = c >> 2, q = c & 3;
        float v = (row < 512)
            ? kernels[DD * G4D + row * G4D + g * DD + nbase + q]
            : rec_kernels[DD * G4D + (row - 512) * G4D + g * DD + nbase + q];
        sm[OFF_W1 + idx] = v;
    }
    // W_out slice
    for (int idx = tid; idx < 512 * 2; idx += TPB) {
        int k = idx >> 1, c = idx & 1;
        sm[OFF_WOUT + idx] = W_out[k * WW + cbase + c];
    }
    // biases
    if (tid < 16) {
        int g = tid >> 2, q = tid & 3;
        sm[OFF_BIAS + tid] = biases[g * DD + nbase + q];
    } else if (tid < 32) {
        int c = tid - 16, g = c >> 2, q = c & 3;
        sm[OFF_BIAS + tid] = biases[G4D + g * DD + nbase + q];
    } else if (tid < 34) {
        sm[OFF_BIAS + tid] = b_out[cbase + tid - 32];
    }

    // ---- global state init (every launch: graph replays) ----
    for (int i = gt; i < 2 * BB * DD; i += gstride) {
        (&g_h[0][0][0][0])[i] = init_h[i];
        (&g_c[0][0][0])[i] = init_c[i];
    }
    for (int i = gt; i < BB * WW; i += gstride) {
        (&g_prev[0][0])[i] = rand_prev[i];
    }
    // cbias = b_in + cond @ W_in[256:,:]
    for (int i = gt; i < BB * DD; i += gstride) {
        const int b = i >> 9, dc = i & (DD - 1);
        const float* cn = inputs + b * FF;
        float s = b_in[dc];
#pragma unroll 4
        for (int k = 0; k < FF; k++)
            s = fmaf(cn[k], W_in[(WW + k) * DD + dc], s);
        (&g_cbias[0][0])[i] = s;
    }
    grid_barrier();

    // ---- M0 = W_in[0:256] @ K0 (this CTA's 16 cols) -> smem W0 rows 0..255 ----
    for (int idx = tid; idx < 256 * 16; idx += TPB) {
        int r = idx >> 4, c = idx & 15, g = c >> 2, q = c & 3;
        const int col = g * DD + nbase + q;
        float s = 0.0f;
#pragma unroll 8
        for (int d = 0; d < DD; d++)
            s = fmaf(W_in[r * DD + d], kernels[d * G4D + col], s);
        sm[OFF_W0 + r * 16 + c] = s;
    }
    // ---- cvec = cbias @ K0 (this CTA's 16 cols) ----
    for (int idx = tid; idx < BB * 16; idx += TPB) {
        int b = idx >> 4, c = idx & 15, g = c >> 2, q = c & 3;
        const int col = g * DD + nbase + q;
        float s = 0.0f;
#pragma unroll 8
        for (int d = 0; d < DD; d++)
            s = fmaf(g_cbias[b][d], kernels[d * G4D + col], s);
        sm[OFF_CVEC + b * 16 + c] = s;
    }
    __syncthreads();

    // ---- time loop: 3 phases, 3 barriers ----
    for (int t = 0; t < TT; t++) {
        const int p = t & 1;
        // L0': z0 = prev@M0 + h0_prev@R0 + bias0 + cvec
        phase_L(&g_prev[0][0], 256, WW, &g_h[p][0][0][0], DD, 768,
                sm + OFF_W0, sm + OFF_BIAS, sm + OFF_CVEC,
                &g_c[0][0][0], &g_h[1 - p][0][0][0], sm);
        grid_barrier();
        // L1: z1 = h0_new@K1 + h1_prev@R1 + bias1
        phase_L(&g_h[1 - p][0][0][0], 512, DD, &g_h[p][1][0][0], DD, 1024,
                sm + OFF_W1, sm + OFF_BIAS + 16, (const float*)0,
                &g_c[1][0][0], &g_h[1 - p][1][0][0], sm);
        grid_barrier();
        phase_p3(&g_h[1 - p][1][0][0], sm + OFF_WOUT, sm + OFF_BIAS, out, t, sm);
        grid_barrier();
    }
}

extern "C" void kernel_launch(void* const* d_in, const int* in_sizes, int n_in,
                              void* d_out, int out_size) {
    const float* inputs      = (const float*)d_in[0];
    const float* rand_prev   = (const float*)d_in[1];
    const float* init_h      = (const float*)d_in[2];
    const float* init_c      = (const float*)d_in[3];
    const float* W_in        = (const float*)d_in[4];
    const float* b_in        = (const float*)d_in[5];
    const float* kernels     = (const float*)d_in[6];
    const float* rec_kernels = (const float*)d_in[7];
    const float* biases      = (const float*)d_in[8];
    const float* W_out       = (const float*)d_in[9];
    const float* b_out       = (const float*)d_in[10];
    float* out = (float*)d_out;

    static int attr_done = 0;
    if (!attr_done) {
        cudaFuncSetAttribute(lstm_persistent_kernel,
                             cudaFuncAttributeMaxDynamicSharedMemorySize, SMEM_BYTES);
        attr_done = 1;
    }
    lstm_persistent_kernel<<<NBLK, TPB, SMEM_BYTES>>>(
        inputs, rand_prev, init_h, init_c, W_in, b_in, kernels, rec_kernels,
        biases, W_out, b_out, out);
}